// round 3
// baseline (speedup 1.0000x reference)
#include <cuda_runtime.h>
#include <cstdint>
#include <cstddef>

#define B_ 2
#define H_ 16
#define S_ 2048
#define D_ 128
#define THREADS 512
#define PITCH 132
#define TILE_FLOATS (128*PITCH)          // 16896
#define UNION_OFF (3*TILE_FLOATS)        // 50688 : Q (phase1) / red (phase2) / At[3] (phase3)
#define AT_FLOATS (16*PITCH)             // 2112 per At buffer
#define SMEM_FLOATS (UNION_OFF + 3*AT_FLOATS)   // 57024
#define SMEM_BYTES (SMEM_FLOATS*4)              // 228096

#define SCALE_L2E 0.12751744912f         // (1/sqrt(128)) * log2(e)
#define L2E       1.4426950408889634f

__device__ __forceinline__ unsigned f2tf(float x){
    unsigned u; asm("cvt.rna.tf32.f32 %0, %1;" : "=r"(u) : "f"(x)); return u;
}
__device__ __forceinline__ void mma_tf32(float* c,
    unsigned a0,unsigned a1,unsigned a2,unsigned a3, unsigned b0, unsigned b1){
    asm volatile("mma.sync.aligned.m16n8k8.row.col.f32.tf32.tf32.f32 "
        "{%0,%1,%2,%3}, {%4,%5,%6,%7}, {%8,%9}, {%0,%1,%2,%3};"
        : "+f"(c[0]),"+f"(c[1]),"+f"(c[2]),"+f"(c[3])
        : "r"(a0),"r"(a1),"r"(a2),"r"(a3),"r"(b0),"r"(b1));
}
__device__ __forceinline__ void cpa16(float* dst, const float* src){
    unsigned d = (unsigned)__cvta_generic_to_shared(dst);
    asm volatile("cp.async.cg.shared.global [%0], [%1], 16;" :: "r"(d), "l"(src));
}
#define CP_COMMIT() asm volatile("cp.async.commit_group;")
#define CP_WAIT1()  asm volatile("cp.async.wait_group 1;")
#define CP_WAIT0()  asm volatile("cp.async.wait_group 0;")

// exp2 on the FMA pipe: rint via magic add, deg-4 poly, exponent via bit add.
// valid for t <= 0 (clamped at -126); ~4e-5 rel err.
__device__ __forceinline__ float exp2_fast(float t){
    t = fmaxf(t, -126.0f);
    float r = t + 12582912.0f;           // 1.5*2^23 : n = rint(t) in low bits
    float f = t - (r - 12582912.0f);     // f in [-0.5, 0.5]
    float p = 0.009618129f;
    p = fmaf(p, f, 0.055504109f);
    p = fmaf(p, f, 0.240226507f);
    p = fmaf(p, f, 0.693147181f);
    p = fmaf(p, f, 1.0f);
    return __uint_as_float(__float_as_uint(p) + (__float_as_uint(r) << 23));
}

__device__ __forceinline__ void load_tile(float* dst, const float* src, int tid){
    #pragma unroll
    for (int i=0;i<8;i++){
        int id = tid + i*THREADS;
        cpa16(dst + (id>>5)*PITCH + ((id&31)<<2), src + (id>>5)*D_ + ((id&31)<<2));
    }
}

__global__ __launch_bounds__(THREADS,1)
void attn_kernel(const float* __restrict__ q, const float* __restrict__ k,
                 const float* __restrict__ v, const int* __restrict__ mask,
                 const float* __restrict__ bias, float* __restrict__ out,
                 float* __restrict__ attn)
{
    extern __shared__ float smem[];
    float* qs  = smem + UNION_OFF;       // phase-1 alias
    float* red = smem + UNION_OFF;       // phase-2 alias (Q dead by then)

    const int tid = threadIdx.x, warp = tid>>5, lane = tid&31;
    const int g = lane>>2, ctg = lane&3;
    const int h = blockIdx.x>>1, b = blockIdx.x&1;
    const int q0 = blockIdx.y*16;
    const size_t bh = (size_t)(b*H_+h);
    const float* qp = q + (bh*S_+q0)*(size_t)D_;
    const float* kp = k + bh*(size_t)S_*D_;
    const float* vp = v + bh*(size_t)S_*D_;

    // ---- prologue: Q + K0, K1 ----
    { int r=tid>>5, c4=(tid&31)<<2; cpa16(qs + r*PITCH + c4, qp + r*D_ + c4); }
    load_tile(smem, kp, tid);
    CP_COMMIT();
    load_tile(smem + TILE_FLOATS, kp + 128*D_, tid);
    CP_COMMIT();
    CP_WAIT1(); __syncthreads();

    // convert+permute Q in place: within each 8-col group, col c -> (c&3)*2 + (c>>2)
    if (tid < 256){
        int r = tid>>4, blk = tid&15;
        float* p = qs + r*PITCH + blk*8;
        float t[8];
        #pragma unroll
        for (int i=0;i<8;i++) t[i]=p[i];
        unsigned* up=(unsigned*)p;
        #pragma unroll
        for (int i=0;i<8;i++) up[(i&3)*2 + (i>>2)] = f2tf(t[i]);
    }

    float sacc[16][4];

    // ---- phase 1: QK^T, 16 tiles, 3-stage cp.async pipeline ----
    #pragma unroll
    for (int kt=0; kt<16; ++kt){
        CP_WAIT1(); __syncthreads();
        const float* kb = smem + (kt%3)*TILE_FLOATS;
        float* acc = sacc[kt]; acc[0]=0.f; acc[1]=0.f; acc[2]=0.f; acc[3]=0.f;
        const unsigned* qrowL = (const unsigned*)(qs +  g   *PITCH) + 2*ctg;
        const unsigned* qrowH = (const unsigned*)(qs + (g+8)*PITCH) + 2*ctg;
        const float* krow = kb + (warp*8+g)*PITCH + ctg;
        #pragma unroll
        for (int dk=0; dk<16; ++dk){
            uint2 aL = *(const uint2*)(qrowL + dk*8);
            uint2 aH = *(const uint2*)(qrowH + dk*8);
            unsigned b0 = f2tf(krow[dk*8]);
            unsigned b1 = f2tf(krow[dk*8+4]);
            mma_tf32(acc, aL.x, aH.x, aL.y, aH.y, b0, b1);
        }
        if (kt < 14){
            load_tile(smem + ((kt+2)%3)*TILE_FLOATS, kp + (size_t)(kt+2)*128*D_, tid);
            CP_COMMIT();
        } else {
            // prefetch V0 -> buf1 (kt=14), V1 -> buf2 (kt=15); overlaps softmax
            load_tile(smem + ((kt+2)%3)*TILE_FLOATS, vp + (size_t)(kt-14)*128*D_, tid);
            CP_COMMIT();
        }
    }

    // ---- phase 2: scale+bias+mask (log2 domain), softmax, attn STG ----
    const int colw = warp*8 + 2*ctg;
    const float* bLo = bias + ((size_t)h*S_ + q0+g)*S_ + colw;
    const float* bHi = bLo + 8*(size_t)S_;
    const int*   mLo = mask + ((size_t)b*S_ + q0+g)*S_ + colw;
    const int*   mHi = mLo + 8*(size_t)S_;
    float mxlo=-3.4e38f, mxhi=-3.4e38f;
    #pragma unroll
    for (int kt=0;kt<16;++kt){
        float2 b2l = *(const float2*)(bLo + kt*128);
        float2 b2h = *(const float2*)(bHi + kt*128);
        int2   m2l = *(const int2*)(mLo + kt*128);
        int2   m2h = *(const int2*)(mHi + kt*128);
        float* a = sacc[kt];
        a[0] = m2l.x ? fmaf(b2l.x, L2E, a[0]*SCALE_L2E) : -1e9f;
        a[1] = m2l.y ? fmaf(b2l.y, L2E, a[1]*SCALE_L2E) : -1e9f;
        a[2] = m2h.x ? fmaf(b2h.x, L2E, a[2]*SCALE_L2E) : -1e9f;
        a[3] = m2h.y ? fmaf(b2h.y, L2E, a[3]*SCALE_L2E) : -1e9f;
        mxlo = fmaxf(mxlo, fmaxf(a[0],a[1]));
        mxhi = fmaxf(mxhi, fmaxf(a[2],a[3]));
    }
    mxlo = fmaxf(mxlo, __shfl_xor_sync(~0u, mxlo, 1));
    mxlo = fmaxf(mxlo, __shfl_xor_sync(~0u, mxlo, 2));
    mxhi = fmaxf(mxhi, __shfl_xor_sync(~0u, mxhi, 1));
    mxhi = fmaxf(mxhi, __shfl_xor_sync(~0u, mxhi, 2));
    if (ctg==0){ red[warp*16+g]=mxlo; red[warp*16+8+g]=mxhi; }
    __syncthreads();
    if (tid<16){
        float m=-3.4e38f;
        #pragma unroll
        for (int wi=0; wi<16; ++wi) m = fmaxf(m, red[wi*16+tid]);
        red[256+tid]=m;
    }
    __syncthreads();
    mxlo = red[256+g]; mxhi = red[256+g+8];
    float smlo=0.f, smhi=0.f;
    #pragma unroll
    for (int kt=0;kt<16;++kt){
        float* a = sacc[kt];
        a[0]=exp2_fast(a[0]-mxlo); a[1]=exp2_fast(a[1]-mxlo);
        a[2]=exp2_fast(a[2]-mxhi); a[3]=exp2_fast(a[3]-mxhi);
        smlo += a[0]+a[1]; smhi += a[2]+a[3];
    }
    smlo += __shfl_xor_sync(~0u,smlo,1); smlo += __shfl_xor_sync(~0u,smlo,2);
    smhi += __shfl_xor_sync(~0u,smhi,1); smhi += __shfl_xor_sync(~0u,smhi,2);
    if (ctg==0){ red[warp*16+g]=smlo; red[warp*16+8+g]=smhi; }
    __syncthreads();
    if (tid<16){
        float s=0.f;
        #pragma unroll
        for (int wi=0;wi<16;++wi) s += red[wi*16+tid];
        red[272+tid] = 1.0f/s;
    }
    __syncthreads();
    {
        float invlo = red[272+g], invhi = red[272+g+8];
        float* aLo = attn + (bh*S_+q0+g)*(size_t)S_ + colw;
        float* aHi = aLo + 8*(size_t)S_;
        #pragma unroll
        for (int kt=0;kt<16;++kt){
            float* a=sacc[kt];
            *(float2*)(aLo + kt*128) = make_float2(a[0]*invlo, a[1]*invlo);
            *(float2*)(aHi + kt*128) = make_float2(a[2]*invhi, a[3]*invhi);
        }
    }

    // attn stores must be visible to this CTA's cp.async reads
    __threadfence_block();
    __syncthreads();

    // ---- phase 3: PV = attn @ V, n-slice per warp, 3-deep paired pipeline ----
    const float* attn_base = attn + (bh*S_+q0)*(size_t)S_;
    // prologue: At0, At1 (V0, V1 already in flight from phase 1)
    {
        int r = tid>>5, c4 = (tid&31)<<2;
        cpa16(smem + UNION_OFF + 0*AT_FLOATS + r*PITCH + c4, attn_base + (size_t)r*S_ + 0*128 + c4);
        CP_COMMIT();
        cpa16(smem + UNION_OFF + 1*AT_FLOATS + r*PITCH + c4, attn_base + (size_t)r*S_ + 1*128 + c4);
        CP_COMMIT();
    }

    float oacc[4] = {0.f,0.f,0.f,0.f};
    const int n0 = warp*8;
    #pragma unroll
    for (int jt=0; jt<16; ++jt){
        if (jt<15) { CP_WAIT1(); } else { CP_WAIT0(); }
        __syncthreads();
        const float* vb  = smem + ((jt+1)%3)*TILE_FLOATS;
        const float* atb = smem + UNION_OFF + (jt%3)*AT_FLOATS;
        const float* arL = atb +  g   *PITCH + ctg;
        const float* arH = atb + (g+8)*PITCH + ctg;
        const float* vr  = vb + ctg*PITCH + n0 + g;
        #pragma unroll
        for (int dk=0; dk<16; ++dk){
            unsigned a0 = f2tf(arL[dk*8]);
            unsigned a1 = f2tf(arH[dk*8]);
            unsigned a2 = f2tf(arL[dk*8+4]);
            unsigned a3 = f2tf(arH[dk*8+4]);
            unsigned b0 = f2tf(vr[(dk*8  )*PITCH]);
            unsigned b1 = f2tf(vr[(dk*8+4)*PITCH]);
            mma_tf32(oacc, a0,a1,a2,a3, b0,b1);
        }
        if (jt < 14){
            // paired prefetch: V(jt+2) and At(jt+2) in ONE commit group
            load_tile(smem + ((jt+3)%3)*TILE_FLOATS, vp + (size_t)(jt+2)*128*D_, tid);
            int r = tid>>5, c4 = (tid&31)<<2;
            cpa16(smem + UNION_OFF + ((jt+2)%3)*AT_FLOATS + r*PITCH + c4,
                  attn_base + (size_t)r*S_ + (size_t)(jt+2)*128 + c4);
            CP_COMMIT();
        }
    }

    float* op = out + (bh*S_+q0)*(size_t)D_;
    *(float2*)(op +  g   *D_ + n0 + 2*ctg) = make_float2(oacc[0], oacc[1]);
    *(float2*)(op + (g+8)*D_ + n0 + 2*ctg) = make_float2(oacc[2], oacc[3]);
}

extern "C" void kernel_launch(void* const* d_in, const int* in_sizes, int n_in,
                              void* d_out, int out_size)
{
    const float* q    = (const float*)d_in[0];
    const float* k    = (const float*)d_in[1];
    const float* v    = (const float*)d_in[2];
    const int*   mask = (const int*)  d_in[3];
    const float* bias = (const float*)d_in[4];
    float* out  = (float*)d_out;
    float* attn = out + (size_t)B_*H_*S_*D_;   // tuple output: (out, attn)

    cudaFuncSetAttribute(attn_kernel,
                         cudaFuncAttributeMaxDynamicSharedMemorySize, SMEM_BYTES);
    dim3 grid(2*H_, S_/16);
    attn_kernel<<<grid, THREADS, SMEM_BYTES>>>(q, k, v, mask, bias, out, attn);
}